// round 15
// baseline (speedup 1.0000x reference)
#include <cuda_runtime.h>
#include <math.h>

#define cB 8
#define cS 256
#define cH 768
#define cNH 4
#define cDH 192
#define cV 32000
#define cFF 3072
#define cSTEPS 32
#define cKV 1536
#define PARTCAP (8*1024*1024)

// ---------------- static scratch ----------------
static __device__ float g_bias[cB*cS];
static __device__ float g_KV[3*cB*cS*cKV];
static __device__ float g_xctx[cB*cSTEPS*cH];
static __device__ float g_qkv0[cB*cSTEPS*3*cH];
static __device__ float g_dec[cB*cH];
static __device__ float g_qnew[cB*cH];
static __device__ float g_raw1[cB*cH];
static __device__ float g_h8[cB*cH];
static __device__ float g_x8[cB*cH];
static __device__ float g_ff8[cB*cFF];
static __device__ float g_x1[cB*cSTEPS*cH];
static __device__ float g_hb[cB*cSTEPS*cH];
static __device__ float g_qkv1[cB*cSTEPS*3*cH];
static __device__ float g_qb[cB*cSTEPS*cH];
static __device__ float g_rawb[cB*cSTEPS*cH];
static __device__ float g_ffb[cB*cSTEPS*cFF];
static __device__ float g_part[PARTCAP];
static __device__ int   g_cnt[256];

// ---------------- f32x2 packed-math helpers ----------------
__device__ __forceinline__ unsigned long long pack2(float v)
{
    unsigned long long r;
    asm("mov.b64 %0, {%1, %1};" : "=l"(r) : "f"(v));
    return r;
}
__device__ __forceinline__ void fma2(unsigned long long& d,
                                     unsigned long long a,
                                     unsigned long long b)
{
    asm("fma.rn.f32x2 %0, %1, %2, %0;" : "+l"(d) : "l"(a), "l"(b));
}
__device__ __forceinline__ float2 unpack2(unsigned long long v)
{
    float lo, hi;
    asm("mov.b64 {%0, %1}, %2;" : "=f"(lo), "=f"(hi) : "l"(v));
    return make_float2(lo, hi);
}

// ============ GEMM-64 (R11-proven): BM=64 BN=128 BK=16, 256 thr, 4x8 f32x2, dbuf, fused split-K ============
__global__ __launch_bounds__(256)
void gemm_sk(const float* __restrict__ A, int lda,
             const float* __restrict__ W,
             const float* __restrict__ bias,
             float* __restrict__ C, int ldc,
             float* __restrict__ Cpart, int* __restrict__ cnt,
             int M, int N, int K, int relu)
{
    __shared__ __align__(16) float As[2][16][68];
    __shared__ __align__(16) float Bs[2][16][132];
    __shared__ int s_last;
    const int tid = threadIdx.x;
    const int bm = blockIdx.y * 64;
    const int bn = blockIdx.x * 128;
    const int S = gridDim.z;
    const int Kc = K / S;
    const int kbeg = blockIdx.z * Kc;
    const int ntile = Kc >> 4;
    const int m0 = (tid >> 4) * 4;
    const int n0 = (tid & 15) * 8;
    const int arow = tid >> 2, ac4 = tid & 3;
    const int brow0 = tid >> 2, brow1 = 64 + (tid >> 2);
    unsigned long long acc[4][4] = {};

    {
        int k0 = kbeg;
        int gm = bm + arow;
        float4 a = (gm < M) ? *(const float4*)(A + (size_t)gm * lda + k0 + ac4 * 4)
                            : make_float4(0.f, 0.f, 0.f, 0.f);
        As[0][ac4*4+0][arow] = a.x; As[0][ac4*4+1][arow] = a.y;
        As[0][ac4*4+2][arow] = a.z; As[0][ac4*4+3][arow] = a.w;
        float4 w0 = *(const float4*)(W + (size_t)(bn + brow0) * K + k0 + ac4 * 4);
        float4 w1 = *(const float4*)(W + (size_t)(bn + brow1) * K + k0 + ac4 * 4);
        Bs[0][ac4*4+0][brow0] = w0.x; Bs[0][ac4*4+1][brow0] = w0.y;
        Bs[0][ac4*4+2][brow0] = w0.z; Bs[0][ac4*4+3][brow0] = w0.w;
        Bs[0][ac4*4+0][brow1] = w1.x; Bs[0][ac4*4+1][brow1] = w1.y;
        Bs[0][ac4*4+2][brow1] = w1.z; Bs[0][ac4*4+3][brow1] = w1.w;
    }
    __syncthreads();

    for (int t = 0; t < ntile; t++) {
        const int cur = t & 1, nxt = cur ^ 1;
        const bool has = (t + 1) < ntile;
        float4 pa = make_float4(0.f,0.f,0.f,0.f), pw0, pw1;
        if (has) {
            int k0 = kbeg + (t + 1) * 16;
            int gm = bm + arow;
            if (gm < M) pa = *(const float4*)(A + (size_t)gm * lda + k0 + ac4 * 4);
            pw0 = *(const float4*)(W + (size_t)(bn + brow0) * K + k0 + ac4 * 4);
            pw1 = *(const float4*)(W + (size_t)(bn + brow1) * K + k0 + ac4 * 4);
        }
        #pragma unroll
        for (int kk = 0; kk < 16; kk++) {
            float4 av = *(const float4*)(&As[cur][kk][m0]);
            const ulonglong2* bq = (const ulonglong2*)(&Bs[cur][kk][n0]);
            ulonglong2 bq0 = bq[0], bq1 = bq[1];
            float a0[4] = {av.x, av.y, av.z, av.w};
            #pragma unroll
            for (int i = 0; i < 4; i++) {
                unsigned long long ap = pack2(a0[i]);
                fma2(acc[i][0], ap, bq0.x);
                fma2(acc[i][1], ap, bq0.y);
                fma2(acc[i][2], ap, bq1.x);
                fma2(acc[i][3], ap, bq1.y);
            }
        }
        if (has) {
            As[nxt][ac4*4+0][arow] = pa.x; As[nxt][ac4*4+1][arow] = pa.y;
            As[nxt][ac4*4+2][arow] = pa.z; As[nxt][ac4*4+3][arow] = pa.w;
            Bs[nxt][ac4*4+0][brow0] = pw0.x; Bs[nxt][ac4*4+1][brow0] = pw0.y;
            Bs[nxt][ac4*4+2][brow0] = pw0.z; Bs[nxt][ac4*4+3][brow0] = pw0.w;
            Bs[nxt][ac4*4+0][brow1] = pw1.x; Bs[nxt][ac4*4+1][brow1] = pw1.y;
            Bs[nxt][ac4*4+2][brow1] = pw1.z; Bs[nxt][ac4*4+3][brow1] = pw1.w;
        }
        __syncthreads();
    }

    if (S == 1) {
        #pragma unroll
        for (int i = 0; i < 4; i++) {
            int gm = bm + m0 + i;
            if (gm < M) {
                float o[8];
                #pragma unroll
                for (int p = 0; p < 4; p++) {
                    float2 v = unpack2(acc[i][p]);
                    o[p*2]   = v.x + bias[bn + n0 + p*2];
                    o[p*2+1] = v.y + bias[bn + n0 + p*2+1];
                }
                if (relu) {
                    #pragma unroll
                    for (int j = 0; j < 8; j++) o[j] = fmaxf(o[j], 0.f);
                }
                float* cp = C + (size_t)gm * ldc + bn + n0;
                *(float4*)(cp)     = make_float4(o[0],o[1],o[2],o[3]);
                *(float4*)(cp + 4) = make_float4(o[4],o[5],o[6],o[7]);
            }
        }
        return;
    }

    {
        float* P = Cpart + (size_t)blockIdx.z * M * N;
        #pragma unroll
        for (int i = 0; i < 4; i++) {
            int gm = bm + m0 + i;
            if (gm < M) {
                float2 v0 = unpack2(acc[i][0]);
                float2 v1 = unpack2(acc[i][1]);
                float2 v2 = unpack2(acc[i][2]);
                float2 v3 = unpack2(acc[i][3]);
                float* pp = P + (size_t)gm * N + bn + n0;
                *(float4*)(pp)     = make_float4(v0.x, v0.y, v1.x, v1.y);
                *(float4*)(pp + 4) = make_float4(v2.x, v2.y, v3.x, v3.y);
            }
        }
    }
    __threadfence();
    __syncthreads();
    if (tid == 0) {
        int tix = blockIdx.y * gridDim.x + blockIdx.x;
        int old = atomicAdd(&cnt[tix], 1);
        s_last = (old == S - 1) ? 1 : 0;
        if (s_last) cnt[tix] = 0;
    }
    __syncthreads();
    if (!s_last) return;

    #pragma unroll
    for (int e = 0; e < 8; e++) {
        int lin = e * 256 + tid;
        int r = lin >> 5;
        int c = (lin & 31) * 4;
        int gm = bm + r;
        if (gm >= M) continue;
        const float* P0 = Cpart + (size_t)gm * N + bn + c;
        float4 s = *(const float4*)(P0);
        for (int z = 1; z < S; z++) {
            float4 p = *(const float4*)(P0 + (size_t)z * M * N);
            s.x += p.x; s.y += p.y; s.z += p.z; s.w += p.w;
        }
        float4 bb = *(const float4*)(bias + bn + c);
        s.x += bb.x; s.y += bb.y; s.z += bb.z; s.w += bb.w;
        if (relu) {
            s.x = fmaxf(s.x, 0.f); s.y = fmaxf(s.y, 0.f);
            s.z = fmaxf(s.z, 0.f); s.w = fmaxf(s.w, 0.f);
        }
        *(float4*)(C + (size_t)gm * ldc + bn + c) = s;
    }
}

// ============ GEMV (M=8): warp computes 2 output columns -> N/16 blocks ============
__global__ __launch_bounds__(256)
void gemv_w2(const float* __restrict__ X, int lda,
             const float* __restrict__ W,
             const float* __restrict__ bias,
             float* __restrict__ C, int ldc,
             int N, int K, int relu)
{
    __shared__ float xs[8][768];
    const int tid = threadIdx.x;
    const int lane = tid & 31;
    const int wid = tid >> 5;
    const int n0 = blockIdx.x * 16 + wid * 2;
    float acc[8][2] = {};

    for (int kt = 0; kt < K; kt += 768) {
        #pragma unroll
        for (int i = 0; i < 6; i++) {
            int lin = i * 256 + tid;
            int row = lin / 192, c4 = lin % 192;
            *(float4*)(&xs[row][c4 * 4]) =
                *(const float4*)(X + (size_t)row * lda + kt + c4 * 4);
        }
        __syncthreads();
        #pragma unroll
        for (int i = 0; i < 6; i++) {
            int k = i * 128 + lane * 4;
            float4 w0 = *(const float4*)(W + (size_t)(n0+0) * K + kt + k);
            float4 w1 = *(const float4*)(W + (size_t)(n0+1) * K + kt + k);
            #pragma unroll
            for (int r = 0; r < 8; r++) {
                float4 xv = *(const float4*)(&xs[r][k]);
                acc[r][0] += xv.x*w0.x + xv.y*w0.y + xv.z*w0.z + xv.w*w0.w;
                acc[r][1] += xv.x*w1.x + xv.y*w1.y + xv.z*w1.z + xv.w*w1.w;
            }
        }
        __syncthreads();
    }
    #pragma unroll
    for (int r = 0; r < 8; r++) {
        #pragma unroll
        for (int j = 0; j < 2; j++) {
            float v = acc[r][j];
            #pragma unroll
            for (int o = 16; o; o >>= 1) v += __shfl_xor_sync(0xffffffffu, v, o);
            if (lane == 0) {
                float y = v + bias[n0 + j];
                C[(size_t)r * ldc + n0 + j] = relu ? fmaxf(y, 0.f) : y;
            }
        }
    }
}

// ---------------- cross attention (256 encoder keys, key bias; packed [K|V]) ----------------
__global__ __launch_bounds__(256)
void cross_attn_k(const float* __restrict__ Q, int nq,
                  const float* __restrict__ KV,
                  const float* __restrict__ bias,
                  float* __restrict__ Out)
{
    __shared__ float qs[8][193];
    __shared__ float ks[32][193];
    __shared__ float sc[8][256];
    const int bh = blockIdx.x;
    const int b = bh / cNH, h = bh % cNH;
    const int i0 = blockIdx.y * 8;
    const int ni = min(8, nq - i0);
    const int tid = threadIdx.x;
    const float scale = 0.07216878364870322f;

    for (int idx = tid; idx < ni * cDH; idx += 256) {
        int i = idx / cDH, d = idx % cDH;
        qs[i][d] = Q[(size_t)(b * nq + i0 + i) * cH + h * cDH + d];
    }
    __syncthreads();

    for (int jt = 0; jt < cS; jt += 32) {
        for (int idx = tid; idx < 32 * cDH; idx += 256) {
            int j = idx / cDH, d = idx % cDH;
            ks[j][d] = KV[(size_t)(b * cS + jt + j) * cKV + h * cDH + d];
        }
        __syncthreads();
        {
            int i = tid >> 5, j = tid & 31;
            if (i < ni) {
                float s = 0.f;
                #pragma unroll 8
                for (int d = 0; d < cDH; d++) s += qs[i][d] * ks[j][d];
                sc[i][jt + j] = s * scale + bias[b * cS + jt + j];
            }
        }
        __syncthreads();
    }

    {
        int w = tid >> 5, lane = tid & 31;
        if (w < ni) {
            float mx = -3.4e38f;
            for (int j = lane; j < cS; j += 32) mx = fmaxf(mx, sc[w][j]);
            #pragma unroll
            for (int o = 16; o; o >>= 1) mx = fmaxf(mx, __shfl_xor_sync(0xffffffffu, mx, o));
            float sum = 0.f;
            for (int j = lane; j < cS; j += 32) {
                float e = expf(sc[w][j] - mx);
                sc[w][j] = e; sum += e;
            }
            #pragma unroll
            for (int o = 16; o; o >>= 1) sum += __shfl_xor_sync(0xffffffffu, sum, o);
            float inv = 1.f / sum;
            for (int j = lane; j < cS; j += 32) sc[w][j] *= inv;
        }
    }
    __syncthreads();

    {
        int i = tid >> 5, lane = tid & 31;
        float oacc[6] = {0.f, 0.f, 0.f, 0.f, 0.f, 0.f};
        for (int jt = 0; jt < cS; jt += 32) {
            for (int idx = tid; idx < 32 * cDH; idx += 256) {
                int j = idx / cDH, d = idx % cDH;
                ks[j][d] = KV[(size_t)(b * cS + jt + j) * cKV + cH + h * cDH + d];
            }
            __syncthreads();
            if (i < ni) {
                float p = sc[i][jt + lane];
                #pragma unroll 8
                for (int j = 0; j < 32; j++) {
                    float pj = __shfl_sync(0xffffffffu, p, j);
                    #pragma unroll
                    for (int k = 0; k < 6; k++)
                        oacc[k] += pj * ks[j][lane + 32 * k];
                }
            }
            __syncthreads();
        }
        if (i < ni) {
            #pragma unroll
            for (int k = 0; k < 6; k++)
                Out[(size_t)(b * nq + i0 + i) * cH + h * cDH + lane + 32 * k] = oacc[k];
        }
    }
}

// ---------------- self attention over decoder tokens (L<=32) ----------------
__global__ __launch_bounds__(256)
void self_attn_k(const float* __restrict__ QKV, int rs, int L,
                 float* __restrict__ Out, int lastonly)
{
    __shared__ float ks[32][193];
    __shared__ float sc[32][33];
    const int b = blockIdx.x / cNH, h = blockIdx.x % cNH;
    const int tid = threadIdx.x;
    const float scale = 0.07216878364870322f;

    for (int idx = tid; idx < L * cDH; idx += 256) {
        int j = idx / cDH, d = idx % cDH;
        ks[j][d] = QKV[(size_t)(b * rs + j) * (3 * cH) + cH + h * cDH + d];
    }
    __syncthreads();

    const int i_lo = lastonly ? (L - 1) : 0;
    const int nq2 = lastonly ? 1 : L;
    for (int idx = tid; idx < nq2 * L; idx += 256) {
        int r = idx / L, j = idx % L;
        const float* q = QKV + (size_t)(b * rs + i_lo + r) * (3 * cH) + h * cDH;
        float s = 0.f;
        #pragma unroll 8
        for (int d = 0; d < cDH; d++) s += q[d] * ks[j][d];
        sc[r][j] = s * scale;
    }
    __syncthreads();

    {
        int w = tid >> 5, lane = tid & 31;
        for (int r = w; r < nq2; r += 8) {
            float x = (lane < L) ? sc[r][lane] : -3.4e38f;
            float mx = x;
            #pragma unroll
            for (int o = 16; o; o >>= 1) mx = fmaxf(mx, __shfl_xor_sync(0xffffffffu, mx, o));
            float e = (lane < L) ? expf(x - mx) : 0.f;
            float sum = e;
            #pragma unroll
            for (int o = 16; o; o >>= 1) sum += __shfl_xor_sync(0xffffffffu, sum, o);
            if (lane < L) sc[r][lane] = e / sum;
        }
    }
    __syncthreads();

    for (int idx = tid; idx < L * cDH; idx += 256) {
        int j = idx / cDH, d = idx % cDH;
        ks[j][d] = QKV[(size_t)(b * rs + j) * (3 * cH) + 2 * cH + h * cDH + d];
    }
    __syncthreads();

    if (lastonly) {
        if (tid < cDH) {
            float acc = 0.f;
            for (int j = 0; j < L; j++) acc += sc[0][j] * ks[j][tid];
            Out[(size_t)b * cH + h * cDH + tid] = acc;
        }
    } else {
        int w = tid >> 5, lane = tid & 31;
        for (int r = w; r < L; r += 8) {
            #pragma unroll
            for (int k = 0; k < 6; k++) {
                int d = lane + 32 * k;
                float acc = 0.f;
                for (int j = 0; j < L; j++) acc += sc[r][j] * ks[j][d];
                Out[(size_t)(b * L + r) * cH + h * cDH + d] = acc;
            }
        }
    }
}

// ---------------- fused residual + LayerNorm ----------------
__global__ __launch_bounds__(256)
void add_ln_k(const float* __restrict__ X, int sx,
              const float* __restrict__ Hh, int sh,
              float* __restrict__ Y, int sy, int Lq,
              const float* __restrict__ gamma,
              const float* __restrict__ beta)
{
    const int m = blockIdx.x;
    const int bb = m / Lq, l = m - bb * Lq;
    const float* x = X + ((size_t)bb * sx + l) * cH;
    const float* hh = Hh + ((size_t)bb * sh + l) * cH;
    float* y = Y + ((size_t)bb * sy + l) * cH;
    const int tid = threadIdx.x;
    __shared__ float red[8];

    float v0 = x[tid] + hh[tid];
    float v1 = x[tid + 256] + hh[tid + 256];
    float v2 = x[tid + 512] + hh[tid + 512];
    float s = v0 + v1 + v2;
    #pragma unroll
    for (int o = 16; o; o >>= 1) s += __shfl_xor_sync(0xffffffffu, s, o);
    if ((tid & 31) == 0) red[tid >> 5] = s;
    __syncthreads();
    float tot = 0.f;
    #pragma unroll
    for (int k = 0; k < 8; k++) tot += red[k];
    float mean = tot * (1.f / 768.f);
    float d0 = v0 - mean, d1 = v1 - mean, d2 = v2 - mean;
    float q = d0 * d0 + d1 * d1 + d2 * d2;
    #pragma unroll
    for (int o = 16; o; o >>= 1) q += __shfl_xor_sync(0xffffffffu, q, o);
    __syncthreads();
    if ((tid & 31) == 0) red[tid >> 5] = q;
    __syncthreads();
    float vq = 0.f;
    #pragma unroll
    for (int k = 0; k < 8; k++) vq += red[k];
    float inv = rsqrtf(vq * (1.f / 768.f) + 1e-5f);
    y[tid]       = d0 * inv * gamma[tid]       + beta[tid];
    y[tid + 256] = d1 * inv * gamma[tid + 256] + beta[tid + 256];
    y[tid + 512] = d2 * inv * gamma[tid + 512] + beta[tid + 512];
}

// ---------------- misc ----------------
__global__ void bias_k(const int* __restrict__ mask, float* __restrict__ out)
{
    int i = blockIdx.x * 256 + threadIdx.x;
    if (i < cB * cS) out[i] = (mask[i] == 0) ? -1e9f : 0.f;
}

__global__ void embed0_k(const int* __restrict__ sent, const float* __restrict__ temb,
                         float* __restrict__ dec)
{
    int b = blockIdx.x;
    int s = sent[b];
    for (int d = threadIdx.x; d < cH; d += 256)
        dec[b * cH + d] = temb[s * cH + d];
}

// vectorized argmax + token embed (tie-break: smallest index)
__global__ __launch_bounds__(256)
void argmax_embed_k(const float* __restrict__ logits, int ldl,
                    const float* __restrict__ tok_w,
                    const float* __restrict__ tok_b,
                    float* __restrict__ dec)
{
    const int b = blockIdx.x;
    const float4* row4 = (const float4*)(logits + (size_t)b * ldl);
    const int tid = threadIdx.x;
    float best = -3.4e38f;
    int bidx = 0x7fffffff;
    for (int v4 = tid; v4 < cV / 4; v4 += 256) {
        float4 x = row4[v4];
        int v = v4 * 4;
        if (x.x > best) { best = x.x; bidx = v; }
        if (x.y > best) { best = x.y; bidx = v + 1; }
        if (x.z > best) { best = x.z; bidx = v + 2; }
        if (x.w > best) { best = x.w; bidx = v + 3; }
    }
    __shared__ float sv[256];
    __shared__ int si[256];
    sv[tid] = best; si[tid] = bidx;
    __syncthreads();
    for (int s = 128; s; s >>= 1) {
        if (tid < s) {
            if (sv[tid + s] > sv[tid] || (sv[tid + s] == sv[tid] && si[tid + s] < si[tid])) {
                sv[tid] = sv[tid + s]; si[tid] = si[tid + s];
            }
        }
        __syncthreads();
    }
    int id = si[0];
    for (int d = tid; d < cH; d += 256)
        dec[b * cH + d] = tok_w[(size_t)d * cV + id] + tok_b[d];
}

// ---------------- host ----------------
extern "C" void kernel_launch(void* const* d_in, const int* in_sizes, int n_in,
                              void* d_out, int out_size)
{
    (void)in_sizes; (void)n_in; (void)out_size;
    const float* hs          = (const float*)d_in[0];
    const int*   sent        = (const int*)d_in[1];
    const int*   amask       = (const int*)d_in[2];
    const float* temb        = (const float*)d_in[5];
    const float* ctx_in_w    = (const float*)d_in[6];
    const float* ctx_in_b    = (const float*)d_in[7];
    const float* ctx_out_w   = (const float*)d_in[8];
    const float* ctx_out_b   = (const float*)d_in[9];
    const float* self_in_w   = (const float*)d_in[10];
    const float* self_in_b   = (const float*)d_in[11];
    const float* self_out_w  = (const float*)d_in[12];
    const float* self_out_b  = (const float*)d_in[13];
    const float* cross_in_w  = (const float*)d_in[14];
    const float* cross_in_b  = (const float*)d_in[15];
    const float* cross_out_w = (const float*)d_in[16];
    const float* cross_out_b = (const float*)d_in[17];
    const float* ff1_w       = (const float*)d_in[18];
    const float* ff1_b       = (const float*)d_in[19];
    const float* ff2_w       = (const float*)d_in[20];
    const float* ff2_b       = (const float*)d_in[21];
    const float* norm_g      = (const float*)d_in[22];
    const float* norm_b      = (const float*)d_in[23];
    const float* out_w       = (const float*)d_in[24];
    const float* out_b       = (const float*)d_in[25];
    const float* tok_w       = (const float*)d_in[26];
    const float* tok_b       = (const float*)d_in[27];
    float* out = (float*)d_out;

    float *pBias, *pKV, *pXctx, *pQkv0, *pDec, *pQnew, *pRaw1, *pH8, *pX8, *pFF8;
    float *pX1, *pHb, *pQkv1, *pQb, *pRawb, *pFFb, *pPart;
    int *pCnt;
    cudaGetSymbolAddress((void**)&pBias, g_bias);
    cudaGetSymbolAddress((void**)&pKV,   g_KV);
    cudaGetSymbolAddress((void**)&pXctx, g_xctx);
    cudaGetSymbolAddress((void**)&pQkv0, g_qkv0);
    cudaGetSymbolAddress((void**)&pDec,  g_dec);
    cudaGetSymbolAddress((void**)&pQnew, g_qnew);
    cudaGetSymbolAddress((void**)&pRaw1, g_raw1);
    cudaGetSymbolAddress((void**)&pH8,   g_h8);
    cudaGetSymbolAddress((void**)&pX8,   g_x8);
    cudaGetSymbolAddress((void**)&pFF8,  g_ff8);
    cudaGetSymbolAddress((void**)&pX1,   g_x1);
    cudaGetSymbolAddress((void**)&pHb,   g_hb);
    cudaGetSymbolAddress((void**)&pQkv1, g_qkv1);
    cudaGetSymbolAddress((void**)&pQb,   g_qb);
    cudaGetSymbolAddress((void**)&pRawb, g_rawb);
    cudaGetSymbolAddress((void**)&pFFb,  g_ffb);
    cudaGetSymbolAddress((void**)&pPart, g_part);
    cudaGetSymbolAddress((void**)&pCnt,  g_cnt);

    auto gemv = [](const float* X, int lda, const float* W, const float* bias,
                   float* C, int ldc, int N, int K, int relu) {
        gemv_w2<<<N / 16, 256>>>(X, lda, W, bias, C, ldc, N, K, relu);
    };

    // batch GEMM with fused split-K (R11-proven 4x8 tile)
    auto gemm = [&](const float* A, int lda, const float* W, const float* bias,
                    float* C, int ldc, int M, int N, int K, int relu) {
        if (M == 8) { gemv_w2<<<N / 16, 256>>>(A, lda, W, bias, C, ldc, N, K, relu); return; }
        int gx = N / 128, gy = (M + 63) / 64;
        int g = gx * gy;
        int S = 1;
        while (S < 16 && g * S < 296 && (size_t)(S << 1) * M * N <= (size_t)PARTCAP
               && (K / (S << 1)) % 16 == 0) S <<= 1;
        gemm_sk<<<dim3(gx, gy, S), 256>>>(A, lda, W, bias, C, ldc, pPart, pCnt, M, N, K, relu);
    };

    // ---- precompute: bias + packed K|V for the 3 cross-attn modules ----
    bias_k<<<8, 256>>>(amask, pBias);
    for (int m = 0; m < 3; m++) {
        const float* w  = (m == 0) ? ctx_in_w : cross_in_w + (size_t)(m - 1) * 3 * cH * cH;
        const float* bb = (m == 0) ? ctx_in_b : cross_in_b + (size_t)(m - 1) * 3 * cH;
        gemm(hs, cH, w + (size_t)cH * cH, bb + cH,
             pKV + (size_t)m * cB * cS * cKV, cKV, cB * cS, cKV, cH, 0);
    }

    const float* KV0 = pKV;
    const float* KV1 = pKV + (size_t)1 * cB * cS * cKV;
    const float* KV2 = pKV + (size_t)2 * cB * cS * cKV;

    // ---- generation loop ----
    for (int t = 0; t < cSTEPS; t++) {
        const int L = t + 1;
        const int M = cB * L;

        if (t == 0) embed0_k<<<8, 256>>>(sent, temb, pDec);
        else        argmax_embed_k<<<8, 256>>>(out + (size_t)(t - 1) * cV, cSTEPS * cV,
                                               tok_w, tok_b, pDec);

        // ctx attention for the new token -> cache slot t
        gemv(pDec, cH, ctx_in_w, ctx_in_b, pQnew, cH, cH, cH, 0);
        cross_attn_k<<<dim3(cB * cNH, 1), 256>>>(pQnew, 1, KV0, pBias, pRaw1);
        gemv(pRaw1, cH, ctx_out_w, ctx_out_b, pXctx + (size_t)t * cH, cSTEPS * cH, cH, cH, 0);
        gemv(pXctx + (size_t)t * cH, cSTEPS * cH, self_in_w, self_in_b,
             pQkv0 + (size_t)t * 3 * cH, cSTEPS * 3 * cH, 3 * cH, cH, 0);

        // ---- layer 0 (all L positions) ----
        self_attn_k<<<cB * cNH, 256>>>(pQkv0, cSTEPS, L, pRawb, 0);
        gemm(pRawb, cH, self_out_w, self_out_b, pHb, cH, M, cH, cH, 0);
        add_ln_k<<<M, 256>>>(pXctx, cSTEPS, pHb, L, pX1, L, L,
                             norm_g + 0 * cH, norm_b + 0 * cH);
        gemm(pX1, cH, cross_in_w, cross_in_b, pQb, cH, M, cH, cH, 0);
        cross_attn_k<<<dim3(cB * cNH, (L + 7) / 8), 256>>>(pQb, L, KV1, pBias, pRawb);
        gemm(pRawb, cH, cross_out_w, cross_out_b, pHb, cH, M, cH, cH, 0);
        add_ln_k<<<M, 256>>>(pX1, L, pHb, L, pX1, L, L,
                             norm_g + 1 * cH, norm_b + 1 * cH);
        gemm(pX1, cH, ff1_w, ff1_b, pFFb, cFF, M, cFF, cH, 1);
        gemm(pFFb, cFF, ff2_w, ff2_b, pHb, cH, M, cH, cFF, 0);
        add_ln_k<<<M, 256>>>(pX1, L, pHb, L, pX1, L, L,
                             norm_g + 2 * cH, norm_b + 2 * cH);

        // ---- layer 1 (QKV for all L, rest last-position-only) ----
        gemm(pX1, cH, self_in_w + (size_t)3 * cH * cH, self_in_b + 3 * cH,
             pQkv1, 3 * cH, M, 3 * cH, cH, 0);
        self_attn_k<<<cB * cNH, 256>>>(pQkv1, L, L, pRaw1, 1);
        gemv(pRaw1, cH, self_out_w + (size_t)cH * cH, self_out_b + cH, pH8, cH, cH, cH, 0);
        add_ln_k<<<cB, 256>>>(pX1 + (size_t)(L - 1) * cH, L, pH8, 1, pX8, 1, 1,
                              norm_g + 3 * cH, norm_b + 3 * cH);
        gemv(pX8, cH, cross_in_w + (size_t)3 * cH * cH, cross_in_b + 3 * cH, pQnew, cH, cH, cH, 0);
        cross_attn_k<<<dim3(cB * cNH, 1), 256>>>(pQnew, 1, KV2, pBias, pRaw1);
        gemv(pRaw1, cH, cross_out_w + (size_t)cH * cH, cross_out_b + cH, pH8, cH, cH, cH, 0);
        add_ln_k<<<cB, 256>>>(pX8, 1, pH8, 1, pX8, 1, 1,
                              norm_g + 4 * cH, norm_b + 4 * cH);
        gemv(pX8, cH, ff1_w + (size_t)cFF * cH, ff1_b + cFF, pFF8, cFF, cFF, cH, 1);
        gemv(pFF8, cFF, ff2_w + (size_t)cH * cFF, ff2_b + cH, pH8, cH, cH, cFF, 0);
        add_ln_k<<<cB, 256>>>(pX8, 1, pH8, 1, pX8, 1, 1,
                              norm_g + 5 * cH, norm_b + 5 * cH);

        // ---- logits for this step ----
        gemv(pX8, cH, out_w, out_b, out + (size_t)t * cV, cSTEPS * cV, cV, cH, 0);
    }
}

// round 16
// speedup vs baseline: 1.0018x; 1.0018x over previous
#include <cuda_runtime.h>
#include <math.h>

#define cB 8
#define cS 256
#define cH 768
#define cNH 4
#define cDH 192
#define cV 32000
#define cFF 3072
#define cSTEPS 32
#define cKV 1536
#define PARTCAP (8*1024*1024)

// ---------------- static scratch ----------------
static __device__ float g_bias[cB*cS];
static __device__ float g_KV[3*cB*cS*cKV];
static __device__ float g_xctx[cB*cSTEPS*cH];
static __device__ float g_qkv0[cB*cSTEPS*3*cH];
static __device__ float g_dec[cB*cH];
static __device__ float g_qnew[cB*cH];
static __device__ float g_raw1[cB*cH];
static __device__ float g_h8[cB*cH];
static __device__ float g_x8[cB*cH];
static __device__ float g_ff8[cB*cFF];
static __device__ float g_x1[cB*cSTEPS*cH];
static __device__ float g_hb[cB*cSTEPS*cH];
static __device__ float g_qkv1[cB*cSTEPS*3*cH];
static __device__ float g_qb[cB*cSTEPS*cH];
static __device__ float g_rawb[cB*cSTEPS*cH];
static __device__ float g_ffb[cB*cSTEPS*cFF];
static __device__ float g_part[PARTCAP];
static __device__ int   g_cnt[256];

// ---------------- f32x2 packed-math helpers ----------------
__device__ __forceinline__ unsigned long long pack2(float v)
{
    unsigned long long r;
    asm("mov.b64 %0, {%1, %1};" : "=l"(r) : "f"(v));
    return r;
}
__device__ __forceinline__ void fma2(unsigned long long& d,
                                     unsigned long long a,
                                     unsigned long long b)
{
    asm("fma.rn.f32x2 %0, %1, %2, %0;" : "+l"(d) : "l"(a), "l"(b));
}
__device__ __forceinline__ float2 unpack2(unsigned long long v)
{
    float lo, hi;
    asm("mov.b64 {%0, %1}, %2;" : "=f"(lo), "=f"(hi) : "l"(v));
    return make_float2(lo, hi);
}

// ============ GEMM-64 (R11-proven): BM=64 BN=128 BK=16, 256 thr, 4x8 f32x2, dbuf, fused split-K ============
__global__ __launch_bounds__(256)
void gemm_sk(const float* __restrict__ A, int lda,
             const float* __restrict__ W,
             const float* __restrict__ bias,
             float* __restrict__ C, int ldc,
             float* __restrict__ Cpart, int* __restrict__ cnt,
             int M, int N, int K, int relu)
{
    __shared__ __align__(16) float As[2][16][68];
    __shared__ __align__(16) float Bs[2][16][132];
    __shared__ int s_last;
    const int tid = threadIdx.x;
    const int bm = blockIdx.y * 64;
    const int bn = blockIdx.x * 128;
    const int S = gridDim.z;
    const int Kc = K / S;
    const int kbeg = blockIdx.z * Kc;
    const int ntile = Kc >> 4;
    const int m0 = (tid >> 4) * 4;
    const int n0 = (tid & 15) * 8;
    const int arow = tid >> 2, ac4 = tid & 3;
    const int brow0 = tid >> 2, brow1 = 64 + (tid >> 2);
    unsigned long long acc[4][4] = {};

    {
        int k0 = kbeg;
        int gm = bm + arow;
        float4 a = (gm < M) ? *(const float4*)(A + (size_t)gm * lda + k0 + ac4 * 4)
                            : make_float4(0.f, 0.f, 0.f, 0.f);
        As[0][ac4*4+0][arow] = a.x; As[0][ac4*4+1][arow] = a.y;
        As[0][ac4*4+2][arow] = a.z; As[0][ac4*4+3][arow] = a.w;
        float4 w0 = *(const float4*)(W + (size_t)(bn + brow0) * K + k0 + ac4 * 4);
        float4 w1 = *(const float4*)(W + (size_t)(bn + brow1) * K + k0 + ac4 * 4);
        Bs[0][ac4*4+0][brow0] = w0.x; Bs[0][ac4*4+1][brow0] = w0.y;
        Bs[0][ac4*4+2][brow0] = w0.z; Bs[0][ac4*4+3][brow0] = w0.w;
        Bs[0][ac4*4+0][brow1] = w1.x; Bs[0][ac4*4+1][brow1] = w1.y;
        Bs[0][ac4*4+2][brow1] = w1.z; Bs[0][ac4*4+3][brow1] = w1.w;
    }
    __syncthreads();

    for (int t = 0; t < ntile; t++) {
        const int cur = t & 1, nxt = cur ^ 1;
        const bool has = (t + 1) < ntile;
        float4 pa = make_float4(0.f,0.f,0.f,0.f), pw0, pw1;
        if (has) {
            int k0 = kbeg + (t + 1) * 16;
            int gm = bm + arow;
            if (gm < M) pa = *(const float4*)(A + (size_t)gm * lda + k0 + ac4 * 4);
            pw0 = *(const float4*)(W + (size_t)(bn + brow0) * K + k0 + ac4 * 4);
            pw1 = *(const float4*)(W + (size_t)(bn + brow1) * K + k0 + ac4 * 4);
        }
        #pragma unroll
        for (int kk = 0; kk < 16; kk++) {
            float4 av = *(const float4*)(&As[cur][kk][m0]);
            const ulonglong2* bq = (const ulonglong2*)(&Bs[cur][kk][n0]);
            ulonglong2 bq0 = bq[0], bq1 = bq[1];
            float a0[4] = {av.x, av.y, av.z, av.w};
            #pragma unroll
            for (int i = 0; i < 4; i++) {
                unsigned long long ap = pack2(a0[i]);
                fma2(acc[i][0], ap, bq0.x);
                fma2(acc[i][1], ap, bq0.y);
                fma2(acc[i][2], ap, bq1.x);
                fma2(acc[i][3], ap, bq1.y);
            }
        }
        if (has) {
            As[nxt][ac4*4+0][arow] = pa.x; As[nxt][ac4*4+1][arow] = pa.y;
            As[nxt][ac4*4+2][arow] = pa.z; As[nxt][ac4*4+3][arow] = pa.w;
            Bs[nxt][ac4*4+0][brow0] = pw0.x; Bs[nxt][ac4*4+1][brow0] = pw0.y;
            Bs[nxt][ac4*4+2][brow0] = pw0.z; Bs[nxt][ac4*4+3][brow0] = pw0.w;
            Bs[nxt][ac4*4+0][brow1] = pw1.x; Bs[nxt][ac4*4+1][brow1] = pw1.y;
            Bs[nxt][ac4*4+2][brow1] = pw1.z; Bs[nxt][ac4*4+3][brow1] = pw1.w;
        }
        __syncthreads();
    }

    if (S == 1) {
        #pragma unroll
        for (int i = 0; i < 4; i++) {
            int gm = bm + m0 + i;
            if (gm < M) {
                float o[8];
                #pragma unroll
                for (int p = 0; p < 4; p++) {
                    float2 v = unpack2(acc[i][p]);
                    o[p*2]   = v.x + bias[bn + n0 + p*2];
                    o[p*2+1] = v.y + bias[bn + n0 + p*2+1];
                }
                if (relu) {
                    #pragma unroll
                    for (int j = 0; j < 8; j++) o[j] = fmaxf(o[j], 0.f);
                }
                float* cp = C + (size_t)gm * ldc + bn + n0;
                *(float4*)(cp)     = make_float4(o[0],o[1],o[2],o[3]);
                *(float4*)(cp + 4) = make_float4(o[4],o[5],o[6],o[7]);
            }
        }
        return;
    }

    {
        float* P = Cpart + (size_t)blockIdx.z * M * N;
        #pragma unroll
        for (int i = 0; i < 4; i++) {
            int gm = bm + m0 + i;
            if (gm < M) {
                float2 v0 = unpack2(acc[i][0]);
                float2 v1 = unpack2(acc[i][1]);
                float2 v2 = unpack2(acc[i][2]);
                float2 v3 = unpack2(acc[i][3]);
                float* pp = P + (size_t)gm * N + bn + n0;
                *(float4*)(pp)     = make_float4(v0.x, v0.y, v1.x, v1.y);
                *(float4*)(pp + 4) = make_float4(v2.x, v2.y, v3.x, v3.y);
            }
        }
    }
    __threadfence();
    __syncthreads();
    if (tid == 0) {
        int tix = blockIdx.y * gridDim.x + blockIdx.x;
        int old = atomicAdd(&cnt[tix], 1);
        s_last = (old == S - 1) ? 1 : 0;
        if (s_last) cnt[tix] = 0;
    }
    __syncthreads();
    if (!s_last) return;

    #pragma unroll
    for (int e = 0; e < 8; e++) {
        int lin = e * 256 + tid;
        int r = lin >> 5;
        int c = (lin & 31) * 4;
        int gm = bm + r;
        if (gm >= M) continue;
        const float* P0 = Cpart + (size_t)gm * N + bn + c;
        float4 s = *(const float4*)(P0);
        for (int z = 1; z < S; z++) {
            float4 p = *(const float4*)(P0 + (size_t)z * M * N);
            s.x += p.x; s.y += p.y; s.z += p.z; s.w += p.w;
        }
        float4 bb = *(const float4*)(bias + bn + c);
        s.x += bb.x; s.y += bb.y; s.z += bb.z; s.w += bb.w;
        if (relu) {
            s.x = fmaxf(s.x, 0.f); s.y = fmaxf(s.y, 0.f);
            s.z = fmaxf(s.z, 0.f); s.w = fmaxf(s.w, 0.f);
        }
        *(float4*)(C + (size_t)gm * ldc + bn + c) = s;
    }
}

// ============ GEMV (M=8): warp computes 2 output columns -> N/16 blocks ============
__global__ __launch_bounds__(256)
void gemv_w2(const float* __restrict__ X, int lda,
             const float* __restrict__ W,
             const float* __restrict__ bias,
             float* __restrict__ C, int ldc,
             int N, int K, int relu)
{
    __shared__ float xs[8][768];
    const int tid = threadIdx.x;
    const int lane = tid & 31;
    const int wid = tid >> 5;
    const int n0 = blockIdx.x * 16 + wid * 2;
    float acc[8][2] = {};

    for (int kt = 0; kt < K; kt += 768) {
        #pragma unroll
        for (int i = 0; i < 6; i++) {
            int lin = i * 256 + tid;
            int row = lin / 192, c4 = lin % 192;
            *(float4*)(&xs[row][c4 * 4]) =
                *(const float4*)(X + (size_t)row * lda + kt + c4 * 4);
        }
        __syncthreads();
        #pragma unroll
        for (int i = 0; i < 6; i++) {
            int k = i * 128 + lane * 4;
            float4 w0 = *(const float4*)(W + (size_t)(n0+0) * K + kt + k);
            float4 w1 = *(const float4*)(W + (size_t)(n0+1) * K + kt + k);
            #pragma unroll
            for (int r = 0; r < 8; r++) {
                float4 xv = *(const float4*)(&xs[r][k]);
                acc[r][0] += xv.x*w0.x + xv.y*w0.y + xv.z*w0.z + xv.w*w0.w;
                acc[r][1] += xv.x*w1.x + xv.y*w1.y + xv.z*w1.z + xv.w*w1.w;
            }
        }
        __syncthreads();
    }
    #pragma unroll
    for (int r = 0; r < 8; r++) {
        #pragma unroll
        for (int j = 0; j < 2; j++) {
            float v = acc[r][j];
            #pragma unroll
            for (int o = 16; o; o >>= 1) v += __shfl_xor_sync(0xffffffffu, v, o);
            if (lane == 0) {
                float y = v + bias[n0 + j];
                C[(size_t)r * ldc + n0 + j] = relu ? fmaxf(y, 0.f) : y;
            }
        }
    }
}

// ---------------- cross attention (256 encoder keys, key bias; packed [K|V]) ----------------
__global__ __launch_bounds__(256)
void cross_attn_k(const float* __restrict__ Q, int nq,
                  const float* __restrict__ KV,
                  const float* __restrict__ bias,
                  float* __restrict__ Out)
{
    __shared__ float qs[8][193];
    __shared__ float ks[32][193];
    __shared__ float sc[8][256];
    const int bh = blockIdx.x;
    const int b = bh / cNH, h = bh % cNH;
    const int i0 = blockIdx.y * 8;
    const int ni = min(8, nq - i0);
    const int tid = threadIdx.x;
    const float scale = 0.07216878364870322f;

    for (int idx = tid; idx < ni * cDH; idx += 256) {
        int i = idx / cDH, d = idx % cDH;
        qs[i][d] = Q[(size_t)(b * nq + i0 + i) * cH + h * cDH + d];
    }
    __syncthreads();

    for (int jt = 0; jt < cS; jt += 32) {
        for (int idx = tid; idx < 32 * cDH; idx += 256) {
            int j = idx / cDH, d = idx % cDH;
            ks[j][d] = KV[(size_t)(b * cS + jt + j) * cKV + h * cDH + d];
        }
        __syncthreads();
        {
            int i = tid >> 5, j = tid & 31;
            if (i < ni) {
                float s = 0.f;
                #pragma unroll 8
                for (int d = 0; d < cDH; d++) s += qs[i][d] * ks[j][d];
                sc[i][jt + j] = s * scale + bias[b * cS + jt + j];
            }
        }
        __syncthreads();
    }

    {
        int w = tid >> 5, lane = tid & 31;
        if (w < ni) {
            float mx = -3.4e38f;
            for (int j = lane; j < cS; j += 32) mx = fmaxf(mx, sc[w][j]);
            #pragma unroll
            for (int o = 16; o; o >>= 1) mx = fmaxf(mx, __shfl_xor_sync(0xffffffffu, mx, o));
            float sum = 0.f;
            for (int j = lane; j < cS; j += 32) {
                float e = expf(sc[w][j] - mx);
                sc[w][j] = e; sum += e;
            }
            #pragma unroll
            for (int o = 16; o; o >>= 1) sum += __shfl_xor_sync(0xffffffffu, sum, o);
            float inv = 1.f / sum;
            for (int j = lane; j < cS; j += 32) sc[w][j] *= inv;
        }
    }
    __syncthreads();

    {
        int i = tid >> 5, lane = tid & 31;
        float oacc[6] = {0.f, 0.f, 0.f, 0.f, 0.f, 0.f};
        for (int jt = 0; jt < cS; jt += 32) {
            for (int idx = tid; idx < 32 * cDH; idx += 256) {
                int j = idx / cDH, d = idx % cDH;
                ks[j][d] = KV[(size_t)(b * cS + jt + j) * cKV + cH + h * cDH + d];
            }
            __syncthreads();
            if (i < ni) {
                float p = sc[i][jt + lane];
                #pragma unroll 8
                for (int j = 0; j < 32; j++) {
                    float pj = __shfl_sync(0xffffffffu, p, j);
                    #pragma unroll
                    for (int k = 0; k < 6; k++)
                        oacc[k] += pj * ks[j][lane + 32 * k];
                }
            }
            __syncthreads();
        }
        if (i < ni) {
            #pragma unroll
            for (int k = 0; k < 6; k++)
                Out[(size_t)(b * nq + i0 + i) * cH + h * cDH + lane + 32 * k] = oacc[k];
        }
    }
}

// ---------------- self attention over decoder tokens (L<=32) ----------------
__global__ __launch_bounds__(256)
void self_attn_k(const float* __restrict__ QKV, int rs, int L,
                 float* __restrict__ Out, int lastonly)
{
    __shared__ float ks[32][193];
    __shared__ float sc[32][33];
    const int b = blockIdx.x / cNH, h = blockIdx.x % cNH;
    const int tid = threadIdx.x;
    const float scale = 0.07216878364870322f;

    for (int idx = tid; idx < L * cDH; idx += 256) {
        int j = idx / cDH, d = idx % cDH;
        ks[j][d] = QKV[(size_t)(b * rs + j) * (3 * cH) + cH + h * cDH + d];
    }
    __syncthreads();

    const int i_lo = lastonly ? (L - 1) : 0;
    const int nq2 = lastonly ? 1 : L;
    for (int idx = tid; idx < nq2 * L; idx += 256) {
        int r = idx / L, j = idx % L;
        const float* q = QKV + (size_t)(b * rs + i_lo + r) * (3 * cH) + h * cDH;
        float s = 0.f;
        #pragma unroll 8
        for (int d = 0; d < cDH; d++) s += q[d] * ks[j][d];
        sc[r][j] = s * scale;
    }
    __syncthreads();

    {
        int w = tid >> 5, lane = tid & 31;
        for (int r = w; r < nq2; r += 8) {
            float x = (lane < L) ? sc[r][lane] : -3.4e38f;
            float mx = x;
            #pragma unroll
            for (int o = 16; o; o >>= 1) mx = fmaxf(mx, __shfl_xor_sync(0xffffffffu, mx, o));
            float e = (lane < L) ? expf(x - mx) : 0.f;
            float sum = e;
            #pragma unroll
            for (int o = 16; o; o >>= 1) sum += __shfl_xor_sync(0xffffffffu, sum, o);
            if (lane < L) sc[r][lane] = e / sum;
        }
    }
    __syncthreads();

    for (int idx = tid; idx < L * cDH; idx += 256) {
        int j = idx / cDH, d = idx % cDH;
        ks[j][d] = QKV[(size_t)(b * rs + j) * (3 * cH) + 2 * cH + h * cDH + d];
    }
    __syncthreads();

    if (lastonly) {
        if (tid < cDH) {
            float acc = 0.f;
            for (int j = 0; j < L; j++) acc += sc[0][j] * ks[j][tid];
            Out[(size_t)b * cH + h * cDH + tid] = acc;
        }
    } else {
        int w = tid >> 5, lane = tid & 31;
        for (int r = w; r < L; r += 8) {
            #pragma unroll
            for (int k = 0; k < 6; k++) {
                int d = lane + 32 * k;
                float acc = 0.f;
                for (int j = 0; j < L; j++) acc += sc[r][j] * ks[j][d];
                Out[(size_t)(b * L + r) * cH + h * cDH + d] = acc;
            }
        }
    }
}

// ---------------- fused residual + LayerNorm ----------------
__global__ __launch_bounds__(256)
void add_ln_k(const float* __restrict__ X, int sx,
              const float* __restrict__ Hh, int sh,
              float* __restrict__ Y, int sy, int Lq,
              const float* __restrict__ gamma,
              const float* __restrict__ beta)
{
    const int m = blockIdx.x;
    const int bb = m / Lq, l = m - bb * Lq;
    const float* x = X + ((size_t)bb * sx + l) * cH;
    const float* hh = Hh + ((size_t)bb * sh + l) * cH;
    float* y = Y + ((size_t)bb * sy + l) * cH;
    const int tid = threadIdx.x;
    __shared__ float red[8];

    float v0 = x[tid] + hh[tid];
    float v1 = x[tid + 256] + hh[tid + 256];
    float v2 = x[tid + 512] + hh[tid + 512];
    float s = v0 + v1 + v2;
    #pragma unroll
    for (int o = 16; o; o >>= 1) s += __shfl_xor_sync(0xffffffffu, s, o);
    if ((tid & 31) == 0) red[tid >> 5] = s;
    __syncthreads();
    float tot = 0.f;
    #pragma unroll
    for (int k = 0; k < 8; k++) tot += red[k];
    float mean = tot * (1.f / 768.f);
    float d0 = v0 - mean, d1 = v1 - mean, d2 = v2 - mean;
    float q = d0 * d0 + d1 * d1 + d2 * d2;
    #pragma unroll
    for (int o = 16; o; o >>= 1) q += __shfl_xor_sync(0xffffffffu, q, o);
    __syncthreads();
    if ((tid & 31) == 0) red[tid >> 5] = q;
    __syncthreads();
    float vq = 0.f;
    #pragma unroll
    for (int k = 0; k < 8; k++) vq += red[k];
    float inv = rsqrtf(vq * (1.f / 768.f) + 1e-5f);
    y[tid]       = d0 * inv * gamma[tid]       + beta[tid];
    y[tid + 256] = d1 * inv * gamma[tid + 256] + beta[tid + 256];
    y[tid + 512] = d2 * inv * gamma[tid + 512] + beta[tid + 512];
}

// ---------------- misc ----------------
__global__ void bias_k(const int* __restrict__ mask, float* __restrict__ out)
{
    int i = blockIdx.x * 256 + threadIdx.x;
    if (i < cB * cS) out[i] = (mask[i] == 0) ? -1e9f : 0.f;
}

__global__ void embed0_k(const int* __restrict__ sent, const float* __restrict__ temb,
                         float* __restrict__ dec)
{
    int b = blockIdx.x;
    int s = sent[b];
    for (int d = threadIdx.x; d < cH; d += 256)
        dec[b * cH + d] = temb[s * cH + d];
}

// vectorized argmax + token embed (tie-break: smallest index)
__global__ __launch_bounds__(256)
void argmax_embed_k(const float* __restrict__ logits, int ldl,
                    const float* __restrict__ tok_w,
                    const float* __restrict__ tok_b,
                    float* __restrict__ dec)
{
    const int b = blockIdx.x;
    const float4* row4 = (const float4*)(logits + (size_t)b * ldl);
    const int tid = threadIdx.x;
    float best = -3.4e38f;
    int bidx = 0x7fffffff;
    for (int v4 = tid; v4 < cV / 4; v4 += 256) {
        float4 x = row4[v4];
        int v = v4 * 4;
        if (x.x > best) { best = x.x; bidx = v; }
        if (x.y > best) { best = x.y; bidx = v + 1; }
        if (x.z > best) { best = x.z; bidx = v + 2; }
        if (x.w > best) { best = x.w; bidx = v + 3; }
    }
    __shared__ float sv[256];
    __shared__ int si[256];
    sv[tid] = best; si[tid] = bidx;
    __syncthreads();
    for (int s = 128; s; s >>= 1) {
        if (tid < s) {
            if (sv[tid + s] > sv[tid] || (sv[tid + s] == sv[tid] && si[tid + s] < si[tid])) {
                sv[tid] = sv[tid + s]; si[tid] = si[tid + s];
            }
        }
        __syncthreads();
    }
    int id = si[0];
    for (int d = tid; d < cH; d += 256)
        dec[b * cH + d] = tok_w[(size_t)d * cV + id] + tok_b[d];
}

// ---------------- host ----------------
extern "C" void kernel_launch(void* const* d_in, const int* in_sizes, int n_in,
                              void* d_out, int out_size)
{
    (void)in_sizes; (void)n_in; (void)out_size;
    const float* hs          = (const float*)d_in[0];
    const int*   sent        = (const int*)d_in[1];
    const int*   amask       = (const int*)d_in[2];
    const float* temb        = (const float*)d_in[5];
    const float* ctx_in_w    = (const float*)d_in[6];
    const float* ctx_in_b    = (const float*)d_in[7];
    const float* ctx_out_w   = (const float*)d_in[8];
    const float* ctx_out_b   = (const float*)d_in[9];
    const float* self_in_w   = (const float*)d_in[10];
    const float* self_in_b   = (const float*)d_in[11];
    const float* self_out_w  = (const float*)d_in[12];
    const float* self_out_b  = (const float*)d_in[13];
    const float* cross_in_w  = (const float*)d_in[14];
    const float* cross_in_b  = (const float*)d_in[15];
    const float* cross_out_w = (const float*)d_in[16];
    const float* cross_out_b = (const float*)d_in[17];
    const float* ff1_w       = (const float*)d_in[18];
    const float* ff1_b       = (const float*)d_in[19];
    const float* ff2_w       = (const float*)d_in[20];
    const float* ff2_b       = (const float*)d_in[21];
    const float* norm_g      = (const float*)d_in[22];
    const float* norm_b      = (const float*)d_in[23];
    const float* out_w       = (const float*)d_in[24];
    const float* out_b       = (const float*)d_in[25];
    const float* tok_w       = (const float*)d_in[26];
    const float* tok_b       = (const float*)d_in[27];
    float* out = (float*)d_out;

    float *pBias, *pKV, *pXctx, *pQkv0, *pDec, *pQnew, *pRaw1, *pH8, *pX8, *pFF8;
    float *pX1, *pHb, *pQkv1, *pQb, *pRawb, *pFFb, *pPart;
    int *pCnt;
    cudaGetSymbolAddress((void**)&pBias, g_bias);
    cudaGetSymbolAddress((void**)&pKV,   g_KV);
    cudaGetSymbolAddress((void**)&pXctx, g_xctx);
    cudaGetSymbolAddress((void**)&pQkv0, g_qkv0);
    cudaGetSymbolAddress((void**)&pDec,  g_dec);
    cudaGetSymbolAddress((void**)&pQnew, g_qnew);
    cudaGetSymbolAddress((void**)&pRaw1, g_raw1);
    cudaGetSymbolAddress((void**)&pH8,   g_h8);
    cudaGetSymbolAddress((void**)&pX8,   g_x8);
    cudaGetSymbolAddress((void**)&pFF8,  g_ff8);
    cudaGetSymbolAddress((void**)&pX1,   g_x1);
    cudaGetSymbolAddress((void**)&pHb,   g_hb);
    cudaGetSymbolAddress((void**)&pQkv1, g_qkv1);
    cudaGetSymbolAddress((void**)&pQb,   g_qb);
    cudaGetSymbolAddress((void**)&pRawb, g_rawb);
    cudaGetSymbolAddress((void**)&pFFb,  g_ffb);
    cudaGetSymbolAddress((void**)&pPart, g_part);
    cudaGetSymbolAddress((void**)&pCnt,  g_cnt);

    auto gemv = [](const float* X, int lda, const float* W, const float* bias,
                   float* C, int ldc, int N, int K, int relu) {
        gemv_w2<<<N / 16, 256>>>(X, lda, W, bias, C, ldc, N, K, relu);
    };

    // batch GEMM with fused split-K (R11-proven 4x8 tile)
    auto gemm = [&](const float* A, int lda, const float* W, const float* bias,
                    float* C, int ldc, int M, int N, int K, int relu) {
        if (M == 8) { gemv_w2<<<N / 16, 256>>>(A, lda, W, bias, C, ldc, N, K, relu); return; }
        int gx = N / 128, gy = (M + 63) / 64;
        int g = gx * gy;
        int S = 1;
        while (S < 16 && g * S < 296 && (size_t)(S << 1) * M * N <= (size_t)PARTCAP
               && (K / (S << 1)) % 16 == 0) S <<= 1;
        gemm_sk<<<dim3(gx, gy, S), 256>>>(A, lda, W, bias, C, ldc, pPart, pCnt, M, N, K, relu);
    };

    // ---- precompute: bias + packed K|V for the 3 cross-attn modules ----
    bias_k<<<8, 256>>>(amask, pBias);
    for (int m = 0; m < 3; m++) {
        const float* w  = (m == 0) ? ctx_in_w : cross_in_w + (size_t)(m - 1) * 3 * cH * cH;
        const float* bb = (m == 0) ? ctx_in_b : cross_in_b + (size_t)(m - 1) * 3 * cH;
        gemm(hs, cH, w + (size_t)cH * cH, bb + cH,
             pKV + (size_t)m * cB * cS * cKV, cKV, cB * cS, cKV, cH, 0);
    }

    const float* KV0 = pKV;
    const float* KV1 = pKV + (size_t)1 * cB * cS * cKV;
    const float* KV2 = pKV + (size_t)2 * cB * cS * cKV;

    // ---- generation loop ----
    for (int t = 0; t < cSTEPS; t++) {
        const int L = t + 1;
        const int M = cB * L;

        if (t == 0) embed0_k<<<8, 256>>>(sent, temb, pDec);
        else        argmax_embed_k<<<8, 256>>>(out + (size_t)(t - 1) * cV, cSTEPS * cV,
                                               tok_w, tok_b, pDec);

        // ctx attention for the new token -> cache slot t
        gemv(pDec, cH, ctx_in_w, ctx_in_b, pQnew, cH, cH, cH, 0);
        cross_attn_k<<<dim3(cB * cNH, 1), 256>>>(pQnew, 1, KV0, pBias, pRaw1);
        gemv(pRaw1, cH, ctx_out_w, ctx_out_b, pXctx + (size_t)t * cH, cSTEPS * cH, cH, cH, 0);
        gemv(pXctx + (size_t)t * cH, cSTEPS * cH, self_in_w, self_in_b,
             pQkv0 + (size_t)t * 3 * cH, cSTEPS * 3 * cH, 3 * cH, cH, 0);

        // ---- layer 0 (all L positions) ----
        self_attn_k<<<cB * cNH, 256>>>(pQkv0, cSTEPS, L, pRawb, 0);
        gemm(pRawb, cH, self_out_w, self_out_b, pHb, cH, M, cH, cH, 0);
        add_ln_k<<<M, 256>>>(pXctx, cSTEPS, pHb, L, pX1, L, L,
                             norm_g + 0 * cH, norm_b + 0 * cH);
        gemm(pX1, cH, cross_in_w, cross_in_b, pQb, cH, M, cH, cH, 0);
        cross_attn_k<<<dim3(cB * cNH, (L + 7) / 8), 256>>>(pQb, L, KV1, pBias, pRawb);
        gemm(pRawb, cH, cross_out_w, cross_out_b, pHb, cH, M, cH, cH, 0);
        add_ln_k<<<M, 256>>>(pX1, L, pHb, L, pX1, L, L,
                             norm_g + 1 * cH, norm_b + 1 * cH);
        gemm(pX1, cH, ff1_w, ff1_b, pFFb, cFF, M, cFF, cH, 1);
        gemm(pFFb, cFF, ff2_w, ff2_b, pHb, cH, M, cH, cFF, 0);
        add_ln_k<<<M, 256>>>(pX1, L, pHb, L, pX1, L, L,
                             norm_g + 2 * cH, norm_b + 2 * cH);

        // ---- layer 1 (QKV for all L, rest last-position-only) ----
        gemm(pX1, cH, self_in_w + (size_t)3 * cH * cH, self_in_b + 3 * cH,
             pQkv1, 3 * cH, M, 3 * cH, cH, 0);
        self_attn_k<<<cB * cNH, 256>>>(pQkv1, L, L, pRaw1, 1);
        gemv(pRaw1, cH, self_out_w + (size_t)cH * cH, self_out_b + cH, pH8, cH, cH, cH, 0);
        add_ln_k<<<cB, 256>>>(pX1 + (size_t)(L - 1) * cH, L, pH8, 1, pX8, 1, 1,
                              norm_g + 3 * cH, norm_b + 3 * cH);
        gemv(pX8, cH, cross_in_w + (size_t)3 * cH * cH, cross_in_b + 3 * cH, pQnew, cH, cH, cH, 0);
        cross_attn_k<<<dim3(cB * cNH, 1), 256>>>(pQnew, 1, KV2, pBias, pRaw1);
        gemv(pRaw1, cH, cross_out_w + (size_t)cH * cH, cross_out_b + cH, pH8, cH, cH, cH, 0);
        add_ln_k<<<cB, 256>>>(pX8, 1, pH8, 1, pX8, 1, 1,
                              norm_g + 4 * cH, norm_b + 4 * cH);
        gemv(pX8, cH, ff1_w + (size_t)cFF * cH, ff1_b + cFF, pFF8, cFF, cFF, cH, 1);
        gemv(pFF8, cFF, ff2_w + (size_t)cH * cFF, ff2_b + cH, pH8, cH, cH, cFF, 0);
        add_ln_k<<<cB, 256>>>(pX8, 1, pH8, 1, pX8, 1, 1,
                              norm_g + 5 * cH, norm_b + 5 * cH);

        // ---- logits for this step ----
        gemv(pX8, cH, out_w, out_b, out + (size_t)t * cV, cSTEPS * cV, cV, cH, 0);
    }
}

// round 17
// speedup vs baseline: 1.1555x; 1.1535x over previous
#include <cuda_runtime.h>
#include <math.h>

#define cB 8
#define cS 256
#define cH 768
#define cNH 4
#define cDH 192
#define cV 32000
#define cFF 3072
#define cSTEPS 32
#define cKV 1536
#define PARTCAP (8*1024*1024)

// ---------------- static scratch ----------------
static __device__ float g_bias[cB*cS];
static __device__ float g_KV[3*cB*cS*cKV];
static __device__ float g_xctx[cB*cSTEPS*cH];
static __device__ float g_qkv0[cB*cSTEPS*3*cH];
static __device__ float g_dec[cB*cH];
static __device__ float g_qnew[cB*cH];
static __device__ float g_raw1[cB*cH];
static __device__ float g_h8[cB*cH];
static __device__ float g_x8[cB*cH];
static __device__ float g_ff8[cB*cFF];
static __device__ float g_x1[cB*cSTEPS*cH];
static __device__ float g_hb[cB*cSTEPS*cH];
static __device__ float g_qkv1[cB*cSTEPS*3*cH];
static __device__ float g_qb[cB*cSTEPS*cH];
static __device__ float g_rawb[cB*cSTEPS*cH];
static __device__ float g_ffb[cB*cSTEPS*cFF];
static __device__ float g_part[PARTCAP];
static __device__ int   g_cnt[256];

// ---------------- tf32 helpers ----------------
__device__ __forceinline__ void splitf(float x, unsigned& hi, unsigned& lo)
{
    asm("cvt.rna.tf32.f32 %0, %1;" : "=r"(hi) : "f"(x));
    float l = x - __uint_as_float(hi);
    asm("cvt.rna.tf32.f32 %0, %1;" : "=r"(lo) : "f"(l));
}
__device__ __forceinline__ void mma8(float* c, const unsigned* a, const unsigned* b)
{
    asm volatile("mma.sync.aligned.m16n8k8.row.col.f32.tf32.tf32.f32 "
        "{%0,%1,%2,%3}, {%4,%5,%6,%7}, {%8,%9}, {%0,%1,%2,%3};"
        : "+f"(c[0]), "+f"(c[1]), "+f"(c[2]), "+f"(c[3])
        : "r"(a[0]), "r"(a[1]), "r"(a[2]), "r"(a[3]), "r"(b[0]), "r"(b[1]));
}

// ============ GEMM-TC: BM=64 BN=64 BK=16, 256 thr, 3xTF32 mma, dbuf, fused split-K ============
// C[M,N] = A[M,K] @ W[N,K]^T + bias (+relu). Warp grid 2(m) x 4(n); warp tile 32x16.
__global__ __launch_bounds__(256)
void gemm_tc(const float* __restrict__ A, int lda,
             const float* __restrict__ W,
             const float* __restrict__ bias,
             float* __restrict__ C, int ldc,
             float* __restrict__ Cpart, int* __restrict__ cnt,
             int M, int N, int K, int relu)
{
    __shared__ __align__(16) float As[2][16][68];
    __shared__ __align__(16) float Bs[2][16][68];
    __shared__ int s_last;
    const int tid = threadIdx.x;
    const int lane = tid & 31;
    const int wid = tid >> 5;
    const int wm = wid & 1;          // m-warp: 0..1 (32 rows each)
    const int wn = wid >> 1;         // n-warp: 0..3 (16 cols each)
    const int bm = blockIdx.y * 64;
    const int bn = blockIdx.x * 64;
    const int S = gridDim.z;
    const int Kc = K / S;
    const int kbeg = blockIdx.z * Kc;
    const int ntile = Kc >> 4;
    const int row = tid >> 2, c4 = tid & 3;
    const int lq = lane >> 2;        // 0..7
    const int lr = lane & 3;         // 0..3
    float acc[2][2][4] = {};         // [mfrag][nfrag][c0..c3]

    // ---- load tile 0 ----
    {
        int k0 = kbeg;
        int gm = bm + row;
        float4 a = (gm < M) ? *(const float4*)(A + (size_t)gm * lda + k0 + c4 * 4)
                            : make_float4(0.f, 0.f, 0.f, 0.f);
        As[0][c4*4+0][row] = a.x; As[0][c4*4+1][row] = a.y;
        As[0][c4*4+2][row] = a.z; As[0][c4*4+3][row] = a.w;
        float4 w = *(const float4*)(W + (size_t)(bn + row) * K + k0 + c4 * 4);
        Bs[0][c4*4+0][row] = w.x; Bs[0][c4*4+1][row] = w.y;
        Bs[0][c4*4+2][row] = w.z; Bs[0][c4*4+3][row] = w.w;
    }
    __syncthreads();

    for (int t = 0; t < ntile; t++) {
        const int cur = t & 1, nxt = cur ^ 1;
        const bool has = (t + 1) < ntile;
        float4 pa = make_float4(0.f,0.f,0.f,0.f), pw;
        if (has) {
            int k0 = kbeg + (t + 1) * 16;
            int gm = bm + row;
            if (gm < M) pa = *(const float4*)(A + (size_t)gm * lda + k0 + c4 * 4);
            pw = *(const float4*)(W + (size_t)(bn + row) * K + k0 + c4 * 4);
        }
        #pragma unroll
        for (int k8 = 0; k8 < 2; k8++) {
            const int kb = k8 * 8;
            // A fragments (m16k8 row-major): 2 m-frags
            unsigned ahi[2][4], alo[2][4];
            #pragma unroll
            for (int i = 0; i < 2; i++) {
                int mr = wm * 32 + i * 16 + lq;
                float a0 = As[cur][kb + lr    ][mr];
                float a1 = As[cur][kb + lr    ][mr + 8];
                float a2 = As[cur][kb + lr + 4][mr];
                float a3 = As[cur][kb + lr + 4][mr + 8];
                splitf(a0, ahi[i][0], alo[i][0]);
                splitf(a1, ahi[i][1], alo[i][1]);
                splitf(a2, ahi[i][2], alo[i][2]);
                splitf(a3, ahi[i][3], alo[i][3]);
            }
            // B fragments (k8n8 col-major): 2 n-frags
            unsigned bhi[2][2], blo[2][2];
            #pragma unroll
            for (int j = 0; j < 2; j++) {
                int nc = wn * 16 + j * 8 + lq;
                float b0 = Bs[cur][kb + lr    ][nc];
                float b1 = Bs[cur][kb + lr + 4][nc];
                splitf(b0, bhi[j][0], blo[j][0]);
                splitf(b1, bhi[j][1], blo[j][1]);
            }
            #pragma unroll
            for (int i = 0; i < 2; i++)
                #pragma unroll
                for (int j = 0; j < 2; j++) {
                    mma8(acc[i][j], ahi[i], bhi[j]);
                    mma8(acc[i][j], ahi[i], blo[j]);
                    mma8(acc[i][j], alo[i], bhi[j]);
                }
        }
        if (has) {
            As[nxt][c4*4+0][row] = pa.x; As[nxt][c4*4+1][row] = pa.y;
            As[nxt][c4*4+2][row] = pa.z; As[nxt][c4*4+3][row] = pa.w;
            Bs[nxt][c4*4+0][row] = pw.x; Bs[nxt][c4*4+1][row] = pw.y;
            Bs[nxt][c4*4+2][row] = pw.z; Bs[nxt][c4*4+3][row] = pw.w;
        }
        __syncthreads();
    }

    if (S == 1) {
        #pragma unroll
        for (int i = 0; i < 2; i++) {
            #pragma unroll
            for (int j = 0; j < 2; j++) {
                int gm0 = bm + wm * 32 + i * 16 + lq;
                int gm1 = gm0 + 8;
                int gn  = bn + wn * 16 + j * 8 + 2 * lr;
                float b0 = bias[gn], b1 = bias[gn + 1];
                float v0 = acc[i][j][0] + b0, v1 = acc[i][j][1] + b1;
                float v2 = acc[i][j][2] + b0, v3 = acc[i][j][3] + b1;
                if (relu) {
                    v0 = fmaxf(v0, 0.f); v1 = fmaxf(v1, 0.f);
                    v2 = fmaxf(v2, 0.f); v3 = fmaxf(v3, 0.f);
                }
                if (gm0 < M) *(float2*)(C + (size_t)gm0 * ldc + gn) = make_float2(v0, v1);
                if (gm1 < M) *(float2*)(C + (size_t)gm1 * ldc + gn) = make_float2(v2, v3);
            }
        }
        return;
    }

    // write partial (dense [z][M][N])
    {
        float* P = Cpart + (size_t)blockIdx.z * M * N;
        #pragma unroll
        for (int i = 0; i < 2; i++) {
            #pragma unroll
            for (int j = 0; j < 2; j++) {
                int gm0 = bm + wm * 32 + i * 16 + lq;
                int gm1 = gm0 + 8;
                int gn  = bn + wn * 16 + j * 8 + 2 * lr;
                if (gm0 < M) *(float2*)(P + (size_t)gm0 * N + gn) =
                    make_float2(acc[i][j][0], acc[i][j][1]);
                if (gm1 < M) *(float2*)(P + (size_t)gm1 * N + gn) =
                    make_float2(acc[i][j][2], acc[i][j][3]);
            }
        }
    }
    __threadfence();
    __syncthreads();
    if (tid == 0) {
        int tix = blockIdx.y * gridDim.x + blockIdx.x;
        int old = atomicAdd(&cnt[tix], 1);
        s_last = (old == S - 1) ? 1 : 0;
        if (s_last) cnt[tix] = 0;
    }
    __syncthreads();
    if (!s_last) return;

    // reduce 64x64 tile = 1024 f4; 4 f4/thread, fixed z order
    #pragma unroll
    for (int e = 0; e < 4; e++) {
        int lin = e * 256 + tid;
        int r = lin >> 4;
        int c = (lin & 15) * 4;
        int gm = bm + r;
        if (gm >= M) continue;
        const float* P0 = Cpart + (size_t)gm * N + bn + c;
        float4 s = *(const float4*)(P0);
        for (int z = 1; z < S; z++) {
            float4 p = *(const float4*)(P0 + (size_t)z * M * N);
            s.x += p.x; s.y += p.y; s.z += p.z; s.w += p.w;
        }
        float4 bb = *(const float4*)(bias + bn + c);
        s.x += bb.x; s.y += bb.y; s.z += bb.z; s.w += bb.w;
        if (relu) {
            s.x = fmaxf(s.x, 0.f); s.y = fmaxf(s.y, 0.f);
            s.z = fmaxf(s.z, 0.f); s.w = fmaxf(s.w, 0.f);
        }
        *(float4*)(C + (size_t)gm * ldc + bn + c) = s;
    }
}

// ============ GEMV (M=8): warp computes 2 output columns -> N/16 blocks ============
__global__ __launch_bounds__(256)
void gemv_w2(const float* __restrict__ X, int lda,
             const float* __restrict__ W,
             const float* __restrict__ bias,
             float* __restrict__ C, int ldc,
             int N, int K, int relu)
{
    __shared__ float xs[8][768];
    const int tid = threadIdx.x;
    const int lane = tid & 31;
    const int wid = tid >> 5;
    const int n0 = blockIdx.x * 16 + wid * 2;
    float acc[8][2] = {};

    for (int kt = 0; kt < K; kt += 768) {
        #pragma unroll
        for (int i = 0; i < 6; i++) {
            int lin = i * 256 + tid;
            int row = lin / 192, c4 = lin % 192;
            *(float4*)(&xs[row][c4 * 4]) =
                *(const float4*)(X + (size_t)row * lda + kt + c4 * 4);
        }
        __syncthreads();
        #pragma unroll
        for (int i = 0; i < 6; i++) {
            int k = i * 128 + lane * 4;
            float4 w0 = *(const float4*)(W + (size_t)(n0+0) * K + kt + k);
            float4 w1 = *(const float4*)(W + (size_t)(n0+1) * K + kt + k);
            #pragma unroll
            for (int r = 0; r < 8; r++) {
                float4 xv = *(const float4*)(&xs[r][k]);
                acc[r][0] += xv.x*w0.x + xv.y*w0.y + xv.z*w0.z + xv.w*w0.w;
                acc[r][1] += xv.x*w1.x + xv.y*w1.y + xv.z*w1.z + xv.w*w1.w;
            }
        }
        __syncthreads();
    }
    #pragma unroll
    for (int r = 0; r < 8; r++) {
        #pragma unroll
        for (int j = 0; j < 2; j++) {
            float v = acc[r][j];
            #pragma unroll
            for (int o = 16; o; o >>= 1) v += __shfl_xor_sync(0xffffffffu, v, o);
            if (lane == 0) {
                float y = v + bias[n0 + j];
                C[(size_t)r * ldc + n0 + j] = relu ? fmaxf(y, 0.f) : y;
            }
        }
    }
}

// ---------------- cross attention (256 encoder keys, key bias; packed [K|V]) ----------------
__global__ __launch_bounds__(256)
void cross_attn_k(const float* __restrict__ Q, int nq,
                  const float* __restrict__ KV,
                  const float* __restrict__ bias,
                  float* __restrict__ Out)
{
    __shared__ float qs[8][193];
    __shared__ float ks[32][193];
    __shared__ float sc[8][256];
    const int bh = blockIdx.x;
    const int b = bh / cNH, h = bh % cNH;
    const int i0 = blockIdx.y * 8;
    const int ni = min(8, nq - i0);
    const int tid = threadIdx.x;
    const float scale = 0.07216878364870322f;

    for (int idx = tid; idx < ni * cDH; idx += 256) {
        int i = idx / cDH, d = idx % cDH;
        qs[i][d] = Q[(size_t)(b * nq + i0 + i) * cH + h * cDH + d];
    }
    __syncthreads();

    for (int jt = 0; jt < cS; jt += 32) {
        for (int idx = tid; idx < 32 * cDH; idx += 256) {
            int j = idx / cDH, d = idx % cDH;
            ks[j][d] = KV[(size_t)(b * cS + jt + j) * cKV + h * cDH + d];
        }
        __syncthreads();
        {
            int i = tid >> 5, j = tid & 31;
            if (i < ni) {
                float s = 0.f;
                #pragma unroll 8
                for (int d = 0; d < cDH; d++) s += qs[i][d] * ks[j][d];
                sc[i][jt + j] = s * scale + bias[b * cS + jt + j];
            }
        }
        __syncthreads();
    }

    {
        int w = tid >> 5, lane = tid & 31;
        if (w < ni) {
            float mx = -3.4e38f;
            for (int j = lane; j < cS; j += 32) mx = fmaxf(mx, sc[w][j]);
            #pragma unroll
            for (int o = 16; o; o >>= 1) mx = fmaxf(mx, __shfl_xor_sync(0xffffffffu, mx, o));
            float sum = 0.f;
            for (int j = lane; j < cS; j += 32) {
                float e = expf(sc[w][j] - mx);
                sc[w][j] = e; sum += e;
            }
            #pragma unroll
            for (int o = 16; o; o >>= 1) sum += __shfl_xor_sync(0xffffffffu, sum, o);
            float inv = 1.f / sum;
            for (int j = lane; j < cS; j += 32) sc[w][j] *= inv;
        }
    }
    __syncthreads();

    {
        int i = tid >> 5, lane = tid & 31;
        float oacc[6] = {0.f, 0.f, 0.f, 0.f, 0.f, 0.f};
        for (int jt = 0; jt < cS; jt += 32) {
            for (int idx = tid; idx < 32 * cDH; idx += 256) {
                int j = idx / cDH, d = idx % cDH;
                ks[j][d] = KV[(size_t)(b * cS + jt + j) * cKV + cH + h * cDH + d];
            }
            __syncthreads();
            if (i < ni) {
                float p = sc[i][jt + lane];
                #pragma unroll 8
                for (int j = 0; j < 32; j++) {
                    float pj = __shfl_sync(0xffffffffu, p, j);
                    #pragma unroll
                    for (int k = 0; k < 6; k++)
                        oacc[k] += pj * ks[j][lane + 32 * k];
                }
            }
            __syncthreads();
        }
        if (i < ni) {
            #pragma unroll
            for (int k = 0; k < 6; k++)
                Out[(size_t)(b * nq + i0 + i) * cH + h * cDH + lane + 32 * k] = oacc[k];
        }
    }
}

// ---------------- self attention over decoder tokens (L<=32) ----------------
__global__ __launch_bounds__(256)
void self_attn_k(const float* __restrict__ QKV, int rs, int L,
                 float* __restrict__ Out, int lastonly)
{
    __shared__ float ks[32][193];
    __shared__ float sc[32][33];
    const int b = blockIdx.x / cNH, h = blockIdx.x % cNH;
    const int tid = threadIdx.x;
    const float scale = 0.07216878364870322f;

    for (int idx = tid; idx < L * cDH; idx += 256) {
        int j = idx / cDH, d = idx % cDH;
        ks[j][d] = QKV[(size_t)(b * rs + j) * (3 * cH) + cH + h * cDH + d];
    }
    __syncthreads();

    const int i_lo = lastonly ? (L - 1) : 0;
    const int nq2 = lastonly ? 1 : L;
    for (int idx = tid; idx < nq2 * L; idx += 256) {
        int r = idx / L, j = idx % L;
        const float* q = QKV + (size_t)(b * rs + i_lo + r) * (3 * cH) + h * cDH;
        float s = 0.f;
        #pragma unroll 8
        for (int d = 0; d < cDH; d++) s += q[d] * ks[j][d];
        sc[r][j] = s * scale;
    }
    __syncthreads();

    {
        int w = tid >> 5, lane = tid & 31;
        for (int r = w; r < nq2; r += 8) {
            float x = (lane < L) ? sc[r][lane] : -3.4e38f;
            float mx = x;
            #pragma unroll
            for (int o = 16; o; o >>= 1) mx = fmaxf(mx, __shfl_xor_sync(0xffffffffu, mx, o));
            float e = (lane < L) ? expf(x - mx) : 0.f;
            float sum = e;
            #pragma unroll
            for (int o = 16; o; o >>= 1) sum += __shfl_xor_sync(0xffffffffu, sum, o);
            if (lane < L) sc[r][lane] = e / sum;
        }
    }
    __syncthreads();

    for (int idx = tid; idx < L * cDH; idx += 256) {
        int j = idx / cDH, d = idx % cDH;
        ks[j][d] = QKV[(size_t)(b * rs + j) * (3 * cH) + 2 * cH + h * cDH + d];
    }
    __syncthreads();

    if (lastonly) {
        if (tid < cDH) {
            float acc = 0.f;
            for (int j = 0; j < L; j++) acc += sc[0][j] * ks[j][tid];
            Out[(size_t)b * cH + h * cDH + tid] = acc;
        }
    } else {
        int w = tid >> 5, lane = tid & 31;
        for (int r = w; r < L; r += 8) {
            #pragma unroll
            for (int k = 0; k < 6; k++) {
                int d = lane + 32 * k;
                float acc = 0.f;
                for (int j = 0; j < L; j++) acc += sc[r][j] * ks[j][d];
                Out[(size_t)(b * L + r) * cH + h * cDH + d] = acc;
            }
        }
    }
}

// ---------------- fused residual + LayerNorm ----------------
__global__ __launch_bounds__(256)
void add_ln_k(const float* __restrict__ X, int sx,
              const float* __restrict__ Hh, int sh,
              float* __restrict__ Y, int sy, int Lq,
              const float* __restrict__ gamma,
              const float* __restrict__ beta)
{
    const int m = blockIdx.x;
    const int bb = m / Lq, l = m - bb * Lq;
    const float* x = X + ((size_t)bb * sx + l) * cH;
    const float* hh = Hh + ((size_t)bb * sh + l) * cH;
    float* y = Y + ((size_t)bb * sy + l) * cH;
    const int tid = threadIdx.x;
    __shared__ float red[8];

    float v0 = x[tid] + hh[tid];
    float v1 = x[tid + 256] + hh[tid + 256];
    float v2 = x[tid + 512] + hh[tid + 512];
    float s = v0 + v1 + v2;
    #pragma unroll
    for (int o = 16; o; o >>= 1) s += __shfl_xor_sync(0xffffffffu, s, o);
    if ((tid & 31) == 0) red[tid >> 5] = s;
    __syncthreads();
    float tot = 0.f;
    #pragma unroll
    for (int k = 0; k < 8; k++) tot += red[k];
    float mean = tot * (1.f / 768.f);
    float d0 = v0 - mean, d1 = v1 - mean, d2 = v2 - mean;
    float q = d0 * d0 + d1 * d1 + d2 * d2;
    #pragma unroll
    for (int o = 16; o; o >>= 1) q += __shfl_xor_sync(0xffffffffu, q, o);
    __syncthreads();
    if ((tid & 31) == 0) red[tid >> 5] = q;
    __syncthreads();
    float vq = 0.f;
    #pragma unroll
    for (int k = 0; k < 8; k++) vq += red[k];
    float inv = rsqrtf(vq * (1.f / 768.f) + 1e-5f);
    y[tid]       = d0 * inv * gamma[tid]       + beta[tid];
    y[tid + 256] = d1 * inv * gamma[tid + 256] + beta[tid + 256];
    y[tid + 512] = d2 * inv * gamma[tid + 512] + beta[tid + 512];
}

// ---------------- misc ----------------
__global__ void bias_k(const int* __restrict__ mask, float* __restrict__ out)
{
    int i = blockIdx.x * 256 + threadIdx.x;
    if (i < cB * cS) out[i] = (mask[i] == 0) ? -1e9f : 0.f;
}

__global__ void embed0_k(const int* __restrict__ sent, const float* __restrict__ temb,
                         float* __restrict__ dec)
{
    int b = blockIdx.x;
    int s = sent[b];
    for (int d = threadIdx.x; d < cH; d += 256)
        dec[b * cH + d] = temb[s * cH + d];
}

// vectorized argmax + token embed (tie-break: smallest index)
__global__ __launch_bounds__(256)
void argmax_embed_k(const float* __restrict__ logits, int ldl,
                    const float* __restrict__ tok_w,
                    const float* __restrict__ tok_b,
                    float* __restrict__ dec)
{
    const int b = blockIdx.x;
    const float4* row4 = (const float4*)(logits + (size_t)b * ldl);
    const int tid = threadIdx.x;
    float best = -3.4e38f;
    int bidx = 0x7fffffff;
    for (int v4 = tid; v4 < cV / 4; v4 += 256) {
        float4 x = row4[v4];
        int v = v4 * 4;
        if (x.x > best) { best = x.x; bidx = v; }
        if (x.y > best) { best = x.y; bidx = v + 1; }
        if (x.z > best) { best = x.z; bidx = v + 2; }
        if (x.w > best) { best = x.w; bidx = v + 3; }
    }
    __shared__ float sv[256];
    __shared__ int si[256];
    sv[tid] = best; si[tid] = bidx;
    __syncthreads();
    for (int s = 128; s; s >>= 1) {
        if (tid < s) {
            if (sv[tid + s] > sv[tid] || (sv[tid + s] == sv[tid] && si[tid + s] < si[tid])) {
                sv[tid] = sv[tid + s]; si[tid] = si[tid + s];
            }
        }
        __syncthreads();
    }
    int id = si[0];
    for (int d = tid; d < cH; d += 256)
        dec[b * cH + d] = tok_w[(size_t)d * cV + id] + tok_b[d];
}

// ---------------- host ----------------
extern "C" void kernel_launch(void* const* d_in, const int* in_sizes, int n_in,
                              void* d_out, int out_size)
{
    (void)in_sizes; (void)n_in; (void)out_size;
    const float* hs          = (const float*)d_in[0];
    const int*   sent        = (const int*)d_in[1];
    const int*   amask       = (const int*)d_in[2];
    const float* temb        = (const float*)d_in[5];
    const float* ctx_in_w    = (const float*)d_in[6];
    const float* ctx_in_b    = (const float*)d_in[7];
    const float* ctx_out_w   = (const float*)d_in[8];
    const float* ctx_out_b   = (const float*)d_in[9];
    const float* self_in_w   = (const float*)d_in[10];
    const float* self_in_b   = (const float*)d_in[11];
    const float* self_out_w  = (const float*)d_in[12];
    const float* self_out_b  = (const float*)d_in[13];
    const float* cross_in_w  = (const float*)d_in[14];
    const float* cross_in_b  = (const float*)d_in[15];
    const float* cross_out_w = (const float*)d_in[16];
    const float* cross_out_b = (const float*)d_in[17];
    const float* ff1_w       = (const float*)d_in[18];
    const float* ff1_b       = (const float*)d_in[19];
    const float* ff2_w       = (const float*)d_in[20];
    const float* ff2_b       = (const float*)d_in[21];
    const float* norm_g      = (const float*)d_in[22];
    const float* norm_b      = (const float*)d_in[23];
    const float* out_w       = (const float*)d_in[24];
    const float* out_b       = (const float*)d_in[25];
    const float* tok_w       = (const float*)d_in[26];
    const float* tok_b       = (const float*)d_in[27];
    float* out = (float*)d_out;

    float *pBias, *pKV, *pXctx, *pQkv0, *pDec, *pQnew, *pRaw1, *pH8, *pX8, *pFF8;
    float *pX1, *pHb, *pQkv1, *pQb, *pRawb, *pFFb, *pPart;
    int *pCnt;
    cudaGetSymbolAddress((void**)&pBias, g_bias);
    cudaGetSymbolAddress((void**)&pKV,   g_KV);
    cudaGetSymbolAddress((void**)&pXctx, g_xctx);
    cudaGetSymbolAddress((void**)&pQkv0, g_qkv0);
    cudaGetSymbolAddress((void**)&pDec,  g_dec);
    cudaGetSymbolAddress((void**)&pQnew, g_qnew);
    cudaGetSymbolAddress((void**)&pRaw1, g_raw1);
    cudaGetSymbolAddress((void**)&pH8,   g_h8);
    cudaGetSymbolAddress((void**)&pX8,   g_x8);
    cudaGetSymbolAddress((void**)&pFF8,  g_ff8);
    cudaGetSymbolAddress((void**)&pX1,   g_x1);
    cudaGetSymbolAddress((void**)&pHb,   g_hb);
    cudaGetSymbolAddress((void**)&pQkv1, g_qkv1);
    cudaGetSymbolAddress((void**)&pQb,   g_qb);
    cudaGetSymbolAddress((void**)&pRawb, g_rawb);
    cudaGetSymbolAddress((void**)&pFFb,  g_ffb);
    cudaGetSymbolAddress((void**)&pPart, g_part);
    cudaGetSymbolAddress((void**)&pCnt,  g_cnt);

    auto gemv = [](const float* X, int lda, const float* W, const float* bias,
                   float* C, int ldc, int N, int K, int relu) {
        gemv_w2<<<N / 16, 256>>>(X, lda, W, bias, C, ldc, N, K, relu);
    };

    // batch GEMM: 3xTF32 tensor-core path, fused split-K
    auto gemm = [&](const float* A, int lda, const float* W, const float* bias,
                    float* C, int ldc, int M, int N, int K, int relu) {
        if (M == 8) { gemv_w2<<<N / 16, 256>>>(A, lda, W, bias, C, ldc, N, K, relu); return; }
        int gx = N / 64, gy = (M + 63) / 64;
        int g = gx * gy;
        int S = 1;
        while (S < 16 && g * S < 296 && (size_t)(S << 1) * M * N <= (size_t)PARTCAP
               && (K / (S << 1)) % 16 == 0) S <<= 1;
        gemm_tc<<<dim3(gx, gy, S), 256>>>(A, lda, W, bias, C, ldc, pPart, pCnt, M, N, K, relu);
    };

    // ---- precompute: bias + packed K|V for the 3 cross-attn modules ----
    bias_k<<<8, 256>>>(amask, pBias);
    for (int m = 0; m < 3; m++) {
        const float* w  = (m == 0) ? ctx_in_w : cross_in_w + (size_t)(m - 1) * 3 * cH * cH;
        const float* bb = (m == 0) ? ctx_in_b : cross_in_b + (size_t)(m - 1) * 3 * cH;
        gemm(hs, cH, w + (size_t)cH * cH, bb + cH,
             pKV + (size_t)m * cB * cS * cKV, cKV, cB * cS, cKV, cH, 0);
    }

    const float* KV0 = pKV;
    const float* KV1 = pKV + (size_t)1 * cB * cS * cKV;
    const float* KV2 = pKV + (size_t)2 * cB * cS * cKV;

    // ---- generation loop ----
    for (int t = 0; t < cSTEPS; t++) {
        const int L = t + 1;
        const int M = cB * L;

        if (t == 0) embed0_k<<<8, 256>>>(sent, temb, pDec);
        else        argmax_embed_k<<<8, 256>>>(out + (size_t)(t - 1) * cV, cSTEPS * cV,
                                               tok_w, tok_b, pDec);

        // ctx attention for the new token -> cache slot t
        gemv(pDec, cH, ctx_in_w, ctx_in_b, pQnew, cH, cH, cH, 0);
        cross_attn_k<<<dim3(cB * cNH, 1), 256>>>(pQnew, 1, KV0, pBias, pRaw1);
        gemv(pRaw1, cH, ctx_out_w, ctx_out_b, pXctx + (size_t)t * cH, cSTEPS * cH, cH, cH, 0);
        gemv(pXctx + (size_t)t * cH, cSTEPS * cH, self_in_w, self_in_b,
             pQkv0 + (size_t)t * 3 * cH, cSTEPS * 3 * cH, 3 * cH, cH, 0);

        // ---- layer 0 (all L positions) ----
        self_attn_k<<<cB * cNH, 256>>>(pQkv0, cSTEPS, L, pRawb, 0);
        gemm(pRawb, cH, self_out_w, self_out_b, pHb, cH, M, cH, cH, 0);
        add_ln_k<<<M, 256>>>(pXctx, cSTEPS, pHb, L, pX1, L, L,
                             norm_g + 0 * cH, norm_b + 0 * cH);
        gemm(pX1, cH, cross_in_w, cross_in_b, pQb, cH, M, cH, cH, 0);
        cross_attn_k<<<dim3(cB * cNH, (L + 7) / 8), 256>>>(pQb, L, KV1, pBias, pRawb);
        gemm(pRawb, cH, cross_out_w, cross_out_b, pHb, cH, M, cH, cH, 0);
        add_ln_k<<<M, 256>>>(pX1, L, pHb, L, pX1, L, L,
                             norm_g + 1 * cH, norm_b + 1 * cH);
        gemm(pX1, cH, ff1_w, ff1_b, pFFb, cFF, M, cFF, cH, 1);
        gemm(pFFb, cFF, ff2_w, ff2_b, pHb, cH, M, cH, cFF, 0);
        add_ln_k<<<M, 256>>>(pX1, L, pHb, L, pX1, L, L,
                             norm_g + 2 * cH, norm_b + 2 * cH);

        // ---- layer 1 (QKV for all L, rest last-position-only) ----
        gemm(pX1, cH, self_in_w + (size_t)3 * cH * cH, self_in_b + 3 * cH,
             pQkv1, 3 * cH, M, 3 * cH, cH, 0);
        self_attn_k<<<cB * cNH, 256>>>(pQkv1, L, L, pRaw1, 1);
        gemv(pRaw1, cH, self_out_w + (size_t)cH * cH, self_out_b + cH, pH8, cH, cH, cH, 0);
        add_ln_k<<<cB, 256>>>(pX1 + (size_t)(L - 1) * cH, L, pH8, 1, pX8, 1, 1,
                              norm_g + 3 * cH, norm_b + 3 * cH);
        gemv(pX8, cH, cross_in_w + (size_t)3 * cH * cH, cross_in_b + 3 * cH, pQnew, cH, cH, cH, 0);
        cross_attn_k<<<dim3(cB * cNH, 1), 256>>>(pQnew, 1, KV2, pBias, pRaw1);
        gemv(pRaw1, cH, cross_out_w + (size_t)cH * cH, cross_out_b + cH, pH8, cH, cH, cH, 0);
        add_ln_k<<<cB, 256>>>(pX8, 1, pH8, 1, pX8, 1, 1,
                              norm_g + 4 * cH, norm_b + 4 * cH);
        gemv(pX8, cH, ff1_w + (size_t)cFF * cH, ff1_b + cFF, pFF8, cFF, cFF, cH, 1);
        gemv(pFF8, cFF, ff2_w + (size_t)cH * cFF, ff2_b + cH, pH8, cH, cH, cFF, 0);
        add_ln_k<<<cB, 256>>>(pX8, 1, pH8, 1, pX8, 1, 1,
                              norm_g + 5 * cH, norm_b + 5 * cH);

        // ---- logits for this step ----
        gemv(pX8, cH, out_w, out_b, out + (size_t)t * cV, cSTEPS * cV, cV, cH, 0);
    }
}